// round 4
// baseline (speedup 1.0000x reference)
#include <cuda_runtime.h>
#include <cstdint>
typedef unsigned long long ull;

#define NN 100000
#define NE 1600000
#define DD 128
#define CAP 128                 // adjacency bucket capacity per node (Poisson(16): safe)

// -------- scratch (device globals: no allocation allowed) --------
__device__ __align__(256) float g_h[(size_t)NN * DD];     // 51.2 MB (layer-1 output)
__device__ int g_cnt[NN];
__device__ int g_adj[(size_t)NN * CAP];                    // 51.2 MB padded buckets
__device__ int g_is64;

// -------- init: zero counts; block 0 detects edge dtype --------
__global__ void k_init(const unsigned int* __restrict__ e) {
    int i = blockIdx.x * blockDim.x + threadIdx.x;
    if (i < NN) g_cnt[i] = 0;
    if (blockIdx.x == 0 && threadIdx.x < 32) {
        int bad = 0;
        for (int j = threadIdx.x; j < 256; j += 32)
            if (e[2 * j + 1] != 0u) bad = 1;
        unsigned any = __ballot_sync(0xffffffffu, bad);
        if (threadIdx.x == 0) g_is64 = (any == 0u) ? 1 : 0;
    }
}

// -------- fill padded adjacency buckets --------
__global__ void k_fill(const void* __restrict__ edge) {
    int i = blockIdx.x * blockDim.x + threadIdx.x;
    if (i >= NE) return;
    int s, d;
    if (g_is64) {
        const long long* e = (const long long*)edge;
        s = (int)e[i]; d = (int)e[NE + i];
    } else {
        const int* e = (const int*)edge;
        s = e[i]; d = e[NE + i];
    }
    int pos = atomicAdd(&g_cnt[d], 1);
    if (pos < CAP) g_adj[((size_t)d << 7) + pos] = s;
}

// -------- fused SAGE layer: gather-in-GEMM --------
// out[row,col] = sum_{k<256} A[row,k]*W[col,k]
//   A[:,0:128]   = mean over neighbors of Xin (gathered on the fly into smem)
//   A[:,128:256] = Xin[row]
//   W[:,0:128]=Wl, W[:,128:256]=Wr
// 128x128 block tile, 256 threads, 8x8 f32x2 accum per thread,
// A double-buffered in 64-k chunks; chunk c+1 produced while chunk c FFMAs wait.
#define AS_STRIDE 68
#define AS_SZ (128 * AS_STRIDE)
#define WP_STRIDE 130
#define GSMEM (2 * AS_SZ * 4 + 128 * WP_STRIDE * 8)   // 202752 B

__device__ __forceinline__ void addx2(ull& a, ull b) {
    asm("add.rn.f32x2 %0, %0, %1;" : "+l"(a) : "l"(b));
}

__global__ __launch_bounds__(256, 1)
void k_sage(const float* __restrict__ Xin,
            const float* __restrict__ Wl, const float* __restrict__ Wr,
            const float* __restrict__ bias,
            float* __restrict__ out, int do_relu) {
    extern __shared__ float sm[];
    float* As = sm;                                    // [2][128][68]
    ull* Wp = reinterpret_cast<ull*>(sm + 2 * AS_SZ);  // [128 kp][130]

    int tid = threadIdx.x;
    int row0 = blockIdx.x * 128;
    int wid = tid >> 5, lane = tid & 31;
    int wr = wid & 3, wc = wid >> 2;      // warp tile 4x2 of 32x64
    int lr = lane >> 3, lc = lane & 7;    // lane tile 4x8

    // ---- W pair-transposed into smem: Wp[kp][col] = (W[col,2kp], W[col,2kp+1])
    {
        const float2* w0 = (const float2*)Wl;
        const float2* w1 = (const float2*)Wr;
        for (int i = tid; i < 8192; i += 256) {
            int col = i >> 6, kpl = i & 63;
            float2 v0 = w0[col * 64 + kpl];
            float2 v1 = w1[col * 64 + kpl];
            Wp[kpl * WP_STRIDE + col] = *reinterpret_cast<ull*>(&v0);
            Wp[(kpl + 64) * WP_STRIDE + col] = *reinterpret_cast<ull*>(&v1);
        }
    }

    // ---- chunk producers (write straight to smem buffer c&1) ----
    // chunks 0,1: mean-aggregated neighbors (k off 0 / 64); chunks 2,3: Xin rows.
    auto produce = [&](int c) {
        int b = c & 1;
        int off = (c & 1) * 64;
        if (c < 2) {
            // warp handles 16 rows; lane covers float2 at feature off+2*lane
            const float* Xb = Xin + off + 2 * lane;
#pragma unroll 1
            for (int i = 0; i < 16; i++) {
                int r = wid * 16 + i, row = row0 + r;
                ull a0 = 0, a1 = 0, a2 = 0, a3 = 0;
                float invd = 0.f;
                if (row < NN) {
                    int cnt = min(g_cnt[row], CAP);
                    const int* adj = g_adj + ((size_t)row << 7);
                    int j = 0;
                    for (; j + 4 <= cnt; j += 4) {
                        int n0 = adj[j], n1 = adj[j + 1], n2 = adj[j + 2], n3 = adj[j + 3];
                        ull v0 = *reinterpret_cast<const ull*>(Xb + (size_t)n0 * DD);
                        ull v1 = *reinterpret_cast<const ull*>(Xb + (size_t)n1 * DD);
                        ull v2 = *reinterpret_cast<const ull*>(Xb + (size_t)n2 * DD);
                        ull v3 = *reinterpret_cast<const ull*>(Xb + (size_t)n3 * DD);
                        addx2(a0, v0); addx2(a1, v1); addx2(a2, v2); addx2(a3, v3);
                    }
                    for (; j < cnt; j++) {
                        ull v = *reinterpret_cast<const ull*>(Xb + (size_t)adj[j] * DD);
                        addx2(a0, v);
                    }
                    addx2(a0, a1); addx2(a2, a3); addx2(a0, a2);
                    invd = 1.0f / fmaxf((float)cnt, 1.0f);
                }
                unsigned ivu = __float_as_uint(invd);
                ull iv;
                asm("mov.b64 %0, {%1, %1};" : "=l"(iv) : "r"(ivu));
                asm("mul.rn.f32x2 %0, %0, %1;" : "+l"(a0) : "l"(iv));
                *reinterpret_cast<ull*>(As + b * AS_SZ + r * AS_STRIDE + 2 * lane) = a0;
            }
        } else {
#pragma unroll
            for (int j = 0; j < 8; j++) {
                int i = j * 256 + tid;
                int r = i >> 4, q = i & 15;           // 16 float4 per 64-float row
                int row = row0 + r;
                float4 v = make_float4(0.f, 0.f, 0.f, 0.f);
                if (row < NN)
                    v = *reinterpret_cast<const float4*>(Xin + (size_t)row * DD + off + q * 4);
                *reinterpret_cast<float4*>(As + b * AS_SZ + r * AS_STRIDE + q * 4) = v;
            }
        }
    };

    ull acc[8][8];
#pragma unroll
    for (int r = 0; r < 8; r++)
#pragma unroll
        for (int c = 0; c < 8; c++) acc[r][c] = 0ull;

    produce(0);
    __syncthreads();

    for (int c = 0; c < 4; c++) {
        if (c < 3) produce(c + 1);                    // fills buffer (c+1)&1
        const float* Ab = As + (c & 1) * AS_SZ + (wr * 32 + lr) * AS_STRIDE;
        const ull* Wb = Wp + (c * 32) * WP_STRIDE + wc * 64 + lc;
#pragma unroll 2
        for (int kpl = 0; kpl < 32; kpl++) {
            ull a[8], w[8];
#pragma unroll
            for (int r = 0; r < 8; r++)
                a[r] = *reinterpret_cast<const ull*>(Ab + 4 * r * AS_STRIDE + 2 * kpl);
#pragma unroll
            for (int cc = 0; cc < 8; cc++)
                w[cc] = Wb[kpl * WP_STRIDE + 8 * cc];
#pragma unroll
            for (int r = 0; r < 8; r++)
#pragma unroll
                for (int cc = 0; cc < 8; cc++)
                    asm("fma.rn.f32x2 %0, %1, %2, %0;"
                        : "+l"(acc[r][cc]) : "l"(a[r]), "l"(w[cc]));
        }
        __syncthreads();
    }

    // ---- epilogue: combine halves, bias, relu, store
#pragma unroll
    for (int r = 0; r < 8; r++) {
        int row = row0 + wr * 32 + lr + 4 * r;
        if (row < NN) {
#pragma unroll
            for (int cc = 0; cc < 8; cc++) {
                int col = wc * 64 + lc + 8 * cc;
                float lo = __uint_as_float((unsigned)(acc[r][cc] & 0xffffffffull));
                float hi = __uint_as_float((unsigned)(acc[r][cc] >> 32));
                float v = lo + hi + bias[col];
                if (do_relu) v = fmaxf(v, 0.f);
                out[(size_t)row * DD + col] = v;
            }
        }
    }
}

extern "C" void kernel_launch(void* const* d_in, const int* in_sizes, int n_in,
                              void* d_out, int out_size) {
    const float* x   = (const float*)d_in[0];
    const void*  edg = d_in[1];
    const float* W1l = (const float*)d_in[2];
    const float* b1  = (const float*)d_in[3];
    const float* W1r = (const float*)d_in[4];
    const float* W2l = (const float*)d_in[5];
    const float* b2  = (const float*)d_in[6];
    const float* W2r = (const float*)d_in[7];
    float* out = (float*)d_out;

    cudaFuncSetAttribute(k_sage, cudaFuncAttributeMaxDynamicSharedMemorySize, GSMEM);

    const int node_blocks = (NN + 255) / 256;        // 391
    const int edge_blocks = (NE + 255) / 256;        // 6250
    const int sage_blocks = (NN + 127) / 128;        // 782

    k_init<<<node_blocks, 256>>>((const unsigned int*)edg);
    k_fill<<<edge_blocks, 256>>>(edg);
    k_sage<<<sage_blocks, 256, GSMEM>>>(x, W1l, W1r, b1, g_h, /*relu=*/1);
    k_sage<<<sage_blocks, 256, GSMEM>>>(g_h, W2l, W2r, b2, out, /*relu=*/0);
}

// round 5
// speedup vs baseline: 9.2675x; 9.2675x over previous
#include <cuda_runtime.h>
#include <cstdint>
typedef unsigned long long ull;

#define NN 100000
#define NE 1600000
#define DD 128
#define CAP 128                 // adjacency bucket capacity (Poisson(16): overflow ~0)

// -------- scratch (device globals: no allocation allowed) --------
__device__ __align__(256) float g_agg[(size_t)NN * DD];   // mean-aggregated features
__device__ __align__(256) float g_h[(size_t)NN * DD];     // layer-1 output
__device__ int g_cnt[NN];
__device__ int g_adj[(size_t)NN * CAP];
__device__ int g_is64;

// -------- init: zero counts; warp 0 of block 0 detects edge dtype --------
__global__ void k_init(const unsigned int* __restrict__ e) {
    int i = blockIdx.x * blockDim.x + threadIdx.x;
    if (i < NN) g_cnt[i] = 0;
    if (blockIdx.x == 0 && threadIdx.x < 32) {
        int bad = 0;
        for (int j = threadIdx.x; j < 256; j += 32)
            if (e[2 * j + 1] != 0u) bad = 1;
        unsigned any = __ballot_sync(0xffffffffu, bad);
        if (threadIdx.x == 0) g_is64 = (any == 0u) ? 1 : 0;
    }
}

// -------- fill padded adjacency buckets --------
__global__ void k_fill(const void* __restrict__ edge) {
    int i = blockIdx.x * blockDim.x + threadIdx.x;
    if (i >= NE) return;
    int s, d;
    if (g_is64) {
        const long long* e = (const long long*)edge;
        s = (int)e[i]; d = (int)e[NE + i];
    } else {
        const int* e = (const int*)edge;
        s = e[i]; d = e[NE + i];
    }
    int pos = atomicAdd(&g_cnt[d], 1);
    if (pos < CAP) g_adj[((size_t)d << 7) + pos] = s;
}

// -------- gather: warp per node (cooperative full-row loads), mean to g_agg --------
__global__ __launch_bounds__(256)
void k_gather(const float* __restrict__ xext, int use_h) {
    const float4* __restrict__ X4 =
        reinterpret_cast<const float4*>(use_h ? g_h : xext);
    unsigned node = (blockIdx.x * blockDim.x + threadIdx.x) >> 5;
    int lane = threadIdx.x & 31;
    if (node >= NN) return;
    int cnt = min(g_cnt[node], CAP);
    const int* adj = g_adj + ((size_t)node << 7);
    float4 acc = make_float4(0.f, 0.f, 0.f, 0.f);
    for (int j0 = 0; j0 < cnt; j0 += 32) {
        int nb = min(32, cnt - j0);
        int src = (lane < nb) ? adj[j0 + lane] : 0;
#pragma unroll 4
        for (int t = 0; t < nb; t++) {
            int s = __shfl_sync(0xffffffffu, src, t);
            float4 v = X4[(size_t)s * 32 + lane];
            acc.x += v.x; acc.y += v.y; acc.z += v.z; acc.w += v.w;
        }
    }
    float inv = 1.0f / fmaxf((float)cnt, 1.0f);
    acc.x *= inv; acc.y *= inv; acc.z *= inv; acc.w *= inv;
    reinterpret_cast<float4*>(g_agg)[(size_t)node * 32 + lane] = acc;
}

// -------- fused SAGE layer GEMM (cp.async A pipeline) --------
// out[row,col] = sum_{k<256} A[row,k]*W[col,k]
//   A[:,0:128]=g_agg (mean), A[:,128:256]=X;  W[:,0:128]=Wl, W[:,128:256]=Wr
#define AS_STRIDE 68
#define AS_SZ (128 * AS_STRIDE)
#define WP_STRIDE 130
#define GSMEM (2 * AS_SZ * 4 + 128 * WP_STRIDE * 8)   // 202752 B

__global__ __launch_bounds__(256, 1)
void k_gemm(const float* __restrict__ Xext,
            const float* __restrict__ Wl, const float* __restrict__ Wr,
            const float* __restrict__ bias,
            float* __restrict__ outext,
            int use_h_in, int use_h_out, int do_relu) {
    extern __shared__ float sm[];
    float* As = sm;                                    // [2][128][68]
    ull* Wp = reinterpret_cast<ull*>(sm + 2 * AS_SZ);  // [128 kp][130]
    const float* __restrict__ X = use_h_in ? g_h : Xext;
    float* __restrict__ out = use_h_out ? g_h : outext;

    int tid = threadIdx.x;
    int row0 = blockIdx.x * 128;
    int wid = tid >> 5, lane = tid & 31;
    int wr = wid & 3, wc = wid >> 2;       // warp tile 4x2 of 32x64
    int lr = lane >> 3, lc = lane & 7;     // lane tile 4x8

    // ---- W pair-transposed: Wp[kp][col] = (W[col,2kp], W[col,2kp+1])
    {
        const float2* w0 = (const float2*)Wl;
        const float2* w1 = (const float2*)Wr;
        for (int i = tid; i < 8192; i += 256) {
            int col = i >> 6, kpl = i & 63;
            float2 v0 = w0[col * 64 + kpl];
            float2 v1 = w1[col * 64 + kpl];
            Wp[kpl * WP_STRIDE + col] = *reinterpret_cast<ull*>(&v0);
            Wp[(kpl + 64) * WP_STRIDE + col] = *reinterpret_cast<ull*>(&v1);
        }
    }

    // ---- async A-chunk producer: 8 x cp.async 16B per thread into buffer c&1
    int my_r = tid >> 4, my_q = tid & 15;              // thread's (row, float4) slot base
    auto async_chunk = [&](int c) {
        const float* P = (c < 2) ? g_agg : X;
        int off = (c & 1) * 64;
        int b = c & 1;
#pragma unroll
        for (int j = 0; j < 8; j++) {
            int r = my_r + j * 16;                     // 8 rows, stride 16
            int row = row0 + r;
            const float* gp = (row < NN) ? (P + (size_t)row * DD + off + my_q * 4) : P;
            int sz = (row < NN) ? 16 : 0;
            unsigned sa = (unsigned)__cvta_generic_to_shared(
                As + b * AS_SZ + r * AS_STRIDE + my_q * 4);
            asm volatile("cp.async.ca.shared.global [%0], [%1], 16, %2;"
                         :: "r"(sa), "l"(gp), "r"(sz));
        }
        asm volatile("cp.async.commit_group;");
    };

    ull acc[8][8];
#pragma unroll
    for (int r = 0; r < 8; r++)
#pragma unroll
        for (int c = 0; c < 8; c++) acc[r][c] = 0ull;

    async_chunk(0);
    asm volatile("cp.async.wait_group 0;");
    __syncthreads();

    for (int c = 0; c < 4; c++) {
        if (c < 3) async_chunk(c + 1);                 // overlaps with compute below
        const float* Ab = As + (c & 1) * AS_SZ + (wr * 32 + lr) * AS_STRIDE;
        const ull* Wb = Wp + (c * 32) * WP_STRIDE + wc * 64 + lc;
#pragma unroll 2
        for (int kpl = 0; kpl < 32; kpl++) {
            ull a[8], w[8];
#pragma unroll
            for (int r = 0; r < 8; r++)
                a[r] = *reinterpret_cast<const ull*>(Ab + 4 * r * AS_STRIDE + 2 * kpl);
#pragma unroll
            for (int cc = 0; cc < 8; cc++)
                w[cc] = Wb[kpl * WP_STRIDE + 8 * cc];
#pragma unroll
            for (int r = 0; r < 8; r++)
#pragma unroll
                for (int cc = 0; cc < 8; cc++)
                    asm("fma.rn.f32x2 %0, %1, %2, %0;"
                        : "+l"(acc[r][cc]) : "l"(a[r]), "l"(w[cc]));
        }
        if (c < 3) {
            asm volatile("cp.async.wait_group 0;");
            __syncthreads();
        }
    }

    // ---- epilogue: combine halves, bias, relu, store
#pragma unroll
    for (int r = 0; r < 8; r++) {
        int row = row0 + wr * 32 + lr + 4 * r;
        if (row < NN) {
#pragma unroll
            for (int cc = 0; cc < 8; cc++) {
                int col = wc * 64 + lc + 8 * cc;
                float lo = __uint_as_float((unsigned)(acc[r][cc] & 0xffffffffull));
                float hi = __uint_as_float((unsigned)(acc[r][cc] >> 32));
                float v = lo + hi + bias[col];
                if (do_relu) v = fmaxf(v, 0.f);
                out[(size_t)row * DD + col] = v;
            }
        }
    }
}

extern "C" void kernel_launch(void* const* d_in, const int* in_sizes, int n_in,
                              void* d_out, int out_size) {
    const float* x   = (const float*)d_in[0];
    const void*  edg = d_in[1];
    const float* W1l = (const float*)d_in[2];
    const float* b1  = (const float*)d_in[3];
    const float* W1r = (const float*)d_in[4];
    const float* W2l = (const float*)d_in[5];
    const float* b2  = (const float*)d_in[6];
    const float* W2r = (const float*)d_in[7];
    float* out = (float*)d_out;

    cudaFuncSetAttribute(k_gemm, cudaFuncAttributeMaxDynamicSharedMemorySize, GSMEM);

    const int node_blocks = (NN + 255) / 256;        // 391
    const int edge_blocks = (NE + 255) / 256;        // 6250
    const int gath_blocks = (NN * 32 + 255) / 256;   // 12500 (warp per node)
    const int gemm_blocks = (NN + 127) / 128;        // 782

    k_init<<<node_blocks, 256>>>((const unsigned int*)edg);
    k_fill<<<edge_blocks, 256>>>(edg);

    // Layer 1
    k_gather<<<gath_blocks, 256>>>(x, /*use_h=*/0);
    k_gemm<<<gemm_blocks, 256, GSMEM>>>(x, W1l, W1r, b1, out,
                                        /*use_h_in=*/0, /*use_h_out=*/1, /*relu=*/1);
    // Layer 2
    k_gather<<<gath_blocks, 256>>>(x, /*use_h=*/1);
    k_gemm<<<gemm_blocks, 256, GSMEM>>>(x, W2l, W2r, b2, out,
                                        /*use_h_in=*/1, /*use_h_out=*/0, /*relu=*/0);
}